// round 5
// baseline (speedup 1.0000x reference)
#include <cuda_runtime.h>
#include <cuda_bf16.h>

// Rows = 4194304, features = 16 fp32 per row, output = rows x 3 fp32 one-hot.
// selected = (f11 > 0.5) ? 0 : ((f4+f5 > f6+f7) ? 1 : 2)
//
// HBM-bound stream: 256 MiB read (both 32B sectors of each 64B row needed:
// cols 4-7 -> sector 0, col 11 -> sector 1) + 48 MiB write.
// R2/R3 showed latency hiding is warp-count-driven (RPT4/occ81 beat
// RPT8/occ62). This round: RPT=2 -> MLP_p1=4 (less cross-CTA L1tex-queue
// contention / tail spread), lower regs, more warps.

#define ROWS_PER_THREAD 2

__global__ __launch_bounds__(256)
void gating_kernel(const float4* __restrict__ in,   // 4 float4 per row
                   float2* __restrict__ out,        // 3 float2 per thread
                   int n_rows)
{
    int t = blockIdx.x * blockDim.x + threadIdx.x;
    int row0 = t * ROWS_PER_THREAD;
    if (row0 >= n_rows) return;

    // Front-batch loads (4 per thread) for MLP.
    float4 c47[ROWS_PER_THREAD];
    float  c11[ROWS_PER_THREAD];
#pragma unroll
    for (int i = 0; i < ROWS_PER_THREAD; i++) {
        int r = row0 + i;
        c47[i] = in[r * 4 + 1];            // cols 4..7  (LDG.128)
        c11[i] = in[r * 4 + 2].w;          // col 11     (LDG.32)
    }

    float o[ROWS_PER_THREAD * 3];
#pragma unroll
    for (int i = 0; i < ROWS_PER_THREAD; i++) {
        float cyc = c47[i].x + c47[i].y;   // f4 + f5
        float hf  = c47[i].z + c47[i].w;   // f6 + f7
        bool e0 = c11[i] > 0.5f;
        bool e1 = !e0 && (cyc > hf);
        bool e2 = !e0 && !e1;
        o[i * 3 + 0] = e0 ? 1.0f : 0.0f;
        o[i * 3 + 1] = e1 ? 1.0f : 0.0f;
        o[i * 3 + 2] = e2 ? 1.0f : 0.0f;
    }

    // 2 rows * 3 floats = 6 floats = 3 float2, base = t*24 bytes (8B aligned).
    // Warp covers a contiguous 768B span; L2 write-merge gives full sectors.
    float2* dst = out + t * 3;
    __stcs(&dst[0], make_float2(o[0], o[1]));
    __stcs(&dst[1], make_float2(o[2], o[3]));
    __stcs(&dst[2], make_float2(o[4], o[5]));
}

extern "C" void kernel_launch(void* const* d_in, const int* in_sizes, int n_in,
                              void* d_out, int out_size)
{
    const float* features = (const float*)d_in[0];
    float* out = (float*)d_out;
    int n_rows = in_sizes[0] / 16;                 // 4194304

    int n_threads = n_rows / ROWS_PER_THREAD;      // 2097152 (exact)
    int block = 256;
    int grid = n_threads / block;                  // 8192 (exact)
    gating_kernel<<<grid, block>>>((const float4*)features, (float2*)out, n_rows);
}

// round 6
// speedup vs baseline: 1.0550x; 1.0550x over previous
#include <cuda_runtime.h>
#include <cuda_bf16.h>

// Rows = 4194304, 16 fp32/row (64B), out = rows x 3 fp32 one-hot.
// selected = (f11 > 0.5) ? 0 : ((f4+f5 > f6+f7) ? 1 : 2)
//
// R2-R5: strided per-row loads all plateau at ~6.1 TB/s with DRAM only 77%
// => request-path (L1tex wavefronts, partial sectors) suspected, not HBM.
// This version streams input fully coalesced (memcpy-style), exchanges the
// two per-row predicates via smem, and writes output fully coalesced.

#define NITER 4            // 256 rows per iter -> 1024 rows per block

__global__ __launch_bounds__(256)
void gating_kernel(const float4* __restrict__ in,   // 4 float4 per row
                   float4* __restrict__ out,        // 3 floats per row
                   int n_rows)
{
    __shared__ unsigned char s_e0[2][256];   // f11 > 0.5
    __shared__ unsigned char s_cmp[2][256];  // f4+f5 > f6+f7

    int t = threadIdx.x;
    int j  = t & 3;        // which float4 of the row this thread's loads hit
    int lr = t >> 2;       // local row within each 64-row quarter

    long long block_row0 = (long long)blockIdx.x * (256 * NITER);

#pragma unroll
    for (int it = 0; it < NITER; it++) {
        int p = it & 1;
        long long row0 = block_row0 + (long long)it * 256;
        const float4* src = in + row0 * 4;

        // Fully coalesced: warp reads 512B contiguous per instruction.
        float4 v0 = src[t];
        float4 v1 = src[t + 256];
        float4 v2 = src[t + 512];
        float4 v3 = src[t + 768];

        // float4 #1 of a row = cols 4..7 ; float4 #2 = cols 8..11 (.w = f11)
        if (j == 1) {
            s_cmp[p][lr      ] = (v0.x + v0.y > v0.z + v0.w);
            s_cmp[p][lr +  64] = (v1.x + v1.y > v1.z + v1.w);
            s_cmp[p][lr + 128] = (v2.x + v2.y > v2.z + v2.w);
            s_cmp[p][lr + 192] = (v3.x + v3.y > v3.z + v3.w);
        } else if (j == 2) {
            s_e0[p][lr      ] = (v0.w > 0.5f);
            s_e0[p][lr +  64] = (v1.w > 0.5f);
            s_e0[p][lr + 128] = (v2.w > 0.5f);
            s_e0[p][lr + 192] = (v3.w > 0.5f);
        }
        __syncthreads();

        // 256 rows * 3 floats = 768 floats = 192 float4, fully coalesced.
        if (t < 192) {
            float4* dst = out + (row0 >> 2) * 3;   // row0*3/4, exact
            float o[4];
#pragma unroll
            for (int k = 0; k < 4; k++) {
                int g = 4 * t + k;                 // 0..767
                int r = g / 3;
                int c = g - 3 * r;
                int sel = s_e0[p][r] ? 0 : (s_cmp[p][r] ? 1 : 2);
                o[k] = (sel == c) ? 1.0f : 0.0f;
            }
            __stcs(&dst[t], make_float4(o[0], o[1], o[2], o[3]));
        }
        // double-buffered smem (parity p): one barrier per iter is safe
    }
}

extern "C" void kernel_launch(void* const* d_in, const int* in_sizes, int n_in,
                              void* d_out, int out_size)
{
    const float* features = (const float*)d_in[0];
    float* out = (float*)d_out;
    int n_rows = in_sizes[0] / 16;                  // 4194304

    int rows_per_block = 256 * NITER;               // 1024
    int grid = n_rows / rows_per_block;             // 4096 (exact)
    gating_kernel<<<grid, 256>>>((const float4*)features, (float4*)out, n_rows);
}

// round 7
// speedup vs baseline: 1.0603x; 1.0050x over previous
#include <cuda_runtime.h>
#include <cuda_bf16.h>

// Rows = 4194304, 16 fp32/row (64B), out = rows x 3 fp32 one-hot.
// selected = (f11 > 0.5) ? 0 : ((f4+f5 > f6+f7) ? 1 : 2)
//
// R6 win: fully-coalesced memcpy-style input stream (DRAM 77->83%).
// R7: replace smem+__syncthreads predicate exchange with warp-local
// __ballot_sync. Identical DRAM pattern, zero barriers, zero smem.
//
// Per warp-iter: 32 rows. Lane l loads 4 contiguous float4s (each LDG.128
// covers 8 rows x 512B warp-wide). Row r's predicates live in lanes 4r+1
// (cmp: f4+f5>f6+f7, quarter 1 = cols 4..7) and 4r+2 (e0: f11>0.5,
// quarter 2 .w). Two ballots per 8-row chunk broadcast them warp-wide.
// Lanes 0..23 then write 96 output floats = 24 float4, fully coalesced.

#define NITER 4    // 256 rows per block-iter step -> 1024 rows per block

__global__ __launch_bounds__(256)
void gating_kernel(const float4* __restrict__ in,
                   float4* __restrict__ out,
                   int n_rows)
{
    const unsigned FULL = 0xffffffffu;
    int lane = threadIdx.x & 31;
    int warp = threadIdx.x >> 5;

    long long block_row0 = (long long)blockIdx.x * (256 * NITER);

    // Per-lane constants for the store phase (lanes 0..23):
    // lane covers output floats g = 4*lane .. 4*lane+3, rows r = g/3.
    // Both rows lie in the same 8-row chunk (proven: floor(4l/3) never == 7 mod 8).
    int r0 = (4 * lane) / 3;
    int ch = r0 >> 3;            // which of the 4 load-chunks holds my rows

#pragma unroll
    for (int it = 0; it < NITER; it++) {
        long long row_w = block_row0 + it * 256 + warp * 32;   // warp's 32 rows
        const float4* src = in + row_w * 4;

        // 4 contiguous LDG.128 per lane; each instruction = 512B warp-contiguous.
        float4 v0 = src[lane];
        float4 v1 = src[lane + 32];
        float4 v2 = src[lane + 64];
        float4 v3 = src[lane + 96];

        // Per chunk: bit (4r+2) of me = e0(row r), bit (4r+1) of mc = cmp(row r).
        unsigned me0 = __ballot_sync(FULL, v0.w > 0.5f);
        unsigned mc0 = __ballot_sync(FULL, v0.x + v0.y > v0.z + v0.w);
        unsigned me1 = __ballot_sync(FULL, v1.w > 0.5f);
        unsigned mc1 = __ballot_sync(FULL, v1.x + v1.y > v1.z + v1.w);
        unsigned me2 = __ballot_sync(FULL, v2.w > 0.5f);
        unsigned mc2 = __ballot_sync(FULL, v2.x + v2.y > v2.z + v2.w);
        unsigned me3 = __ballot_sync(FULL, v3.w > 0.5f);
        unsigned mc3 = __ballot_sync(FULL, v3.x + v3.y > v3.z + v3.w);

        if (lane < 24) {
            // Select my chunk's masks (SEL chain, uniform values, no spill).
            unsigned me = (ch & 2) ? ((ch & 1) ? me3 : me2)
                                   : ((ch & 1) ? me1 : me0);
            unsigned mc = (ch & 2) ? ((ch & 1) ? mc3 : mc2)
                                   : ((ch & 1) ? mc1 : mc0);

            float o[4];
#pragma unroll
            for (int k = 0; k < 4; k++) {
                int g = 4 * lane + k;          // 0..95
                int r = g / 3;                 // row within warp tile
                int c = g - 3 * r;             // expert column 0..2
                int sub = r & 7;               // row within chunk
                bool e0 = (me >> (sub * 4 + 2)) & 1;
                bool cm = (mc >> (sub * 4 + 1)) & 1;
                int sel = e0 ? 0 : (cm ? 1 : 2);
                o[k] = (sel == c) ? 1.0f : 0.0f;
            }
            // 32 rows * 3 floats = 24 float4; base = row_w*3 floats (row_w%32==0).
            float4* dst = out + (row_w >> 2) * 3;
            __stcs(&dst[lane], make_float4(o[0], o[1], o[2], o[3]));
        }
    }
}

extern "C" void kernel_launch(void* const* d_in, const int* in_sizes, int n_in,
                              void* d_out, int out_size)
{
    const float* features = (const float*)d_in[0];
    float* out = (float*)d_out;
    int n_rows = in_sizes[0] / 16;                  // 4194304

    int rows_per_block = 256 * NITER;               // 1024
    int grid = n_rows / rows_per_block;             // 4096 (exact)
    gating_kernel<<<grid, 256>>>((const float4*)features, (float4*)out, n_rows);
}

// round 8
// speedup vs baseline: 1.0821x; 1.0205x over previous
#include <cuda_runtime.h>
#include <cuda_bf16.h>

// Rows = 4194304, 16 fp32/row (64B), out = rows x 3 fp32 one-hot.
// selected = (f11 > 0.5) ? 0 : ((f4+f5 > f6+f7) ? 1 : 2)
//
// Fully-coalesced stream (R6 win), warp-ballot predicate exchange (R7),
// R8: finer wave granularity (NITER=2, grid 8192) + all-lane stores
// (3 x STG.32 per lane, each a contiguous 128B warp span) with all
// row/col/shift constants hoisted out of the iteration loop.
//
// Per warp-iter: 32 rows. Lane l loads 4 contiguous float4 (512B/warp/instr).
// Row r's predicates: lane 4r+1 sees cols 4..7 (cmp), lane 4r+2 sees col 11
// in .w (e0). Ballots broadcast them; bit (4*sub+2) of me = e0(row sub),
// bit (4*sub+1) of mc = cmp(row sub), per 8-row chunk.

#define NITER 2    // 256 rows per block-iter -> 512 rows per block

__global__ __launch_bounds__(256)
void gating_kernel(const float4* __restrict__ in,
                   float* __restrict__ out,
                   int n_rows)
{
    const unsigned FULL = 0xffffffffu;
    int lane = threadIdx.x & 31;
    int warp = threadIdx.x >> 5;

    long long block_row0 = (long long)blockIdx.x * (256 * NITER);

    // Hoisted per-lane store constants: store j (j=0,1,2) writes output
    // float g_j = 32*j + lane of the warp's 96-float tile.
    // row_j = g_j / 3 (0..31), col_j = g_j % 3, chunk_j = row_j >> 3.
    int g0 = lane, g1 = lane + 32, g2 = lane + 64;
    int r0 = g0 / 3, r1 = g1 / 3, r2 = g2 / 3;
    int c0 = g0 - 3 * r0, c1 = g1 - 3 * r1, c2 = g2 - 3 * r2;
    int ch0 = r0 >> 3, ch1 = r1 >> 3, ch2 = r2 >> 3;
    int se0 = (r0 & 7) * 4, se1 = (r1 & 7) * 4, se2 = (r2 & 7) * 4;

#pragma unroll
    for (int it = 0; it < NITER; it++) {
        long long row_w = block_row0 + it * 256 + warp * 32;   // warp's 32 rows
        const float4* src = in + row_w * 4;

        float4 v0 = src[lane];
        float4 v1 = src[lane + 32];
        float4 v2 = src[lane + 64];
        float4 v3 = src[lane + 96];

        unsigned m[8];
        m[0] = __ballot_sync(FULL, v0.w > 0.5f);               // me chunk 0
        m[1] = __ballot_sync(FULL, v0.x + v0.y > v0.z + v0.w); // mc chunk 0
        m[2] = __ballot_sync(FULL, v1.w > 0.5f);
        m[3] = __ballot_sync(FULL, v1.x + v1.y > v1.z + v1.w);
        m[4] = __ballot_sync(FULL, v2.w > 0.5f);
        m[5] = __ballot_sync(FULL, v2.x + v2.y > v2.z + v2.w);
        m[6] = __ballot_sync(FULL, v3.w > 0.5f);
        m[7] = __ballot_sync(FULL, v3.x + v3.y > v3.z + v3.w);

        // value for (row, col) given chunk masks
        auto val = [&](int ch, int se, int c) -> float {
            unsigned me = (ch & 2) ? ((ch & 1) ? m[6] : m[4])
                                   : ((ch & 1) ? m[2] : m[0]);
            unsigned mc = (ch & 2) ? ((ch & 1) ? m[7] : m[5])
                                   : ((ch & 1) ? m[3] : m[1]);
            bool e0 = (me >> (se + 2)) & 1;
            bool cm = (mc >> (se + 1)) & 1;
            int sel = e0 ? 0 : (cm ? 1 : 2);
            return (sel == c) ? 1.0f : 0.0f;
        };

        // 96 floats per warp tile; 3 stores, each a contiguous 128B warp span.
        float* dst = out + row_w * 3;
        __stcs(&dst[g0], val(ch0, se0, c0));
        __stcs(&dst[g1], val(ch1, se1, c1));
        __stcs(&dst[g2], val(ch2, se2, c2));
    }
}

extern "C" void kernel_launch(void* const* d_in, const int* in_sizes, int n_in,
                              void* d_out, int out_size)
{
    const float* features = (const float*)d_in[0];
    float* out = (float*)d_out;
    int n_rows = in_sizes[0] / 16;                  // 4194304

    int rows_per_block = 256 * NITER;               // 512
    int grid = n_rows / rows_per_block;             // 8192 (exact)
    gating_kernel<<<grid, 256>>>((const float4*)features, out, n_rows);
}